// round 1
// baseline (speedup 1.0000x reference)
#include <cuda_runtime.h>

// Painting: sequential alpha-composite of N RGBA layers onto a ones canvas.
// canvas = canvas*(1-a) + a*poly,  a = poly[alpha]*0.8
// Per-pixel independent recurrence -> one pass, all state in registers.
//
// Layout: polys[(i*4 + c)*HW + p], out[c*HW + p]. Vectorized as float4 over
// 4 consecutive pixels (HW = 512*512 divisible by 4).

#define OPACITY 0.8f

__global__ __launch_bounds__(256)
void painting_kernel(const float4* __restrict__ polys,
                     float4* __restrict__ out,
                     int planeQuads,   // HW/4
                     int N)
{
    int p = blockIdx.x * blockDim.x + threadIdx.x;
    if (p >= planeQuads) return;

    float4 c0 = make_float4(1.f, 1.f, 1.f, 1.f);
    float4 c1 = c0, c2 = c0, c3 = c0;

    const float4* base = polys + p;
    const long long layerStride = 4LL * planeQuads;

#pragma unroll 2
    for (int i = 0; i < N; ++i) {
        const float4* l = base + (long long)i * layerStride;
        // streaming loads: each byte is read exactly once, skip L2 retention
        float4 p0 = __ldcs(l);
        float4 p1 = __ldcs(l + planeQuads);
        float4 p2 = __ldcs(l + 2 * planeQuads);
        float4 p3 = __ldcs(l + 3 * planeQuads);

        float ax = p3.x * OPACITY;
        float ay = p3.y * OPACITY;
        float az = p3.z * OPACITY;
        float aw = p3.w * OPACITY;

        // c = c*(1-a) + a*p  ==  fma(a, p - c, c)
        c0.x = fmaf(ax, p0.x - c0.x, c0.x);
        c0.y = fmaf(ay, p0.y - c0.y, c0.y);
        c0.z = fmaf(az, p0.z - c0.z, c0.z);
        c0.w = fmaf(aw, p0.w - c0.w, c0.w);

        c1.x = fmaf(ax, p1.x - c1.x, c1.x);
        c1.y = fmaf(ay, p1.y - c1.y, c1.y);
        c1.z = fmaf(az, p1.z - c1.z, c1.z);
        c1.w = fmaf(aw, p1.w - c1.w, c1.w);

        c2.x = fmaf(ax, p2.x - c2.x, c2.x);
        c2.y = fmaf(ay, p2.y - c2.y, c2.y);
        c2.z = fmaf(az, p2.z - c2.z, c2.z);
        c2.w = fmaf(aw, p2.w - c2.w, c2.w);

        c3.x = fmaf(ax, p3.x - c3.x, c3.x);
        c3.y = fmaf(ay, p3.y - c3.y, c3.y);
        c3.z = fmaf(az, p3.z - c3.z, c3.z);
        c3.w = fmaf(aw, p3.w - c3.w, c3.w);
    }

    out[p]                  = c0;
    out[planeQuads + p]     = c1;
    out[2 * planeQuads + p] = c2;
    out[3 * planeQuads + p] = c3;
}

extern "C" void kernel_launch(void* const* d_in, const int* in_sizes, int n_in,
                              void* d_out, int out_size)
{
    const float4* polys = (const float4*)d_in[0];
    float4* out = (float4*)d_out;

    const int H = 512, W = 512;
    const int HW = H * W;
    const int planeQuads = HW / 4;              // 65536
    const int N = in_sizes[0] / (4 * HW);       // 128

    const int threads = 256;
    const int blocks = (planeQuads + threads - 1) / threads;  // 256
    painting_kernel<<<blocks, threads>>>(polys, out, planeQuads, N);
}